// round 6
// baseline (speedup 1.0000x reference)
#include <cuda_runtime.h>
#include <cstdint>
#include <cstddef>

// Problem constants: B=64, S=128, D_MODEL=1024, D_INNER=1024
#define M_TOT 8192
#define KDIM  1024
#define NDIM  1024

// Scratch (allowed: __device__ globals, no allocation in kernel_launch)
__device__ __align__(16) float g_emb_r[(size_t)M_TOT * KDIM]; // rna-rounded embeddings
__device__ __align__(16) float g_wq_t[(size_t)KDIM * NDIM];   // Wq^T, rounded  [N][K]
__device__ __align__(16) float g_wv_t[(size_t)KDIM * NDIM];   // Wv^T, rounded
__device__ __align__(16) float g_wo_t[(size_t)KDIM * NDIM];   // Wo^T, rounded
__device__ __align__(16) float g_mid[(size_t)M_TOT * NDIM];   // g = sigmoid(q)*v, rounded

// ---------------------------------------------------------------------------
// helpers
// ---------------------------------------------------------------------------
__device__ __forceinline__ float rna_tf32(float x) {
    uint32_t y;
    asm("cvt.rna.tf32.f32 %0, %1;" : "=r"(y) : "f"(x));
    return __uint_as_float(y);
}

__device__ __forceinline__ void cp16(uint32_t saddr, const void* gptr) {
    asm volatile("cp.async.cg.shared.global [%0], [%1], 16;" :: "r"(saddr), "l"(gptr));
}

__device__ __forceinline__ void ldsm4(uint32_t r[4], uint32_t saddr) {
    asm volatile("ldmatrix.sync.aligned.m8n8.x4.shared.b16 {%0,%1,%2,%3}, [%4];"
                 : "=r"(r[0]), "=r"(r[1]), "=r"(r[2]), "=r"(r[3]) : "r"(saddr));
}

__device__ __forceinline__ void mma_tf32(float c[4], const uint32_t a[4],
                                         uint32_t b0, uint32_t b1) {
    asm volatile(
        "mma.sync.aligned.m16n8k8.row.col.f32.tf32.tf32.f32 "
        "{%0,%1,%2,%3},{%4,%5,%6,%7},{%8,%9},{%0,%1,%2,%3};"
        : "+f"(c[0]), "+f"(c[1]), "+f"(c[2]), "+f"(c[3])
        : "r"(a[0]), "r"(a[1]), "r"(a[2]), "r"(a[3]), "r"(b0), "r"(b1));
}

__device__ __forceinline__ float sigmf(float x) {
    return 1.0f / (1.0f + __expf(-x));
}

// ---------------------------------------------------------------------------
// Prepass kernels
// ---------------------------------------------------------------------------
__global__ void round4_kernel(const float4* __restrict__ in, float4* __restrict__ out, int n) {
    int i = blockIdx.x * blockDim.x + threadIdx.x;
    if (i < n) {
        float4 t = in[i];
        t.x = rna_tf32(t.x); t.y = rna_tf32(t.y);
        t.z = rna_tf32(t.z); t.w = rna_tf32(t.w);
        out[i] = t;
    }
}

// out[n][k] = rna(in[k][n]) for a 1024x1024 matrix
__global__ void transpose_round_kernel(const float* __restrict__ in, float* __restrict__ out) {
    __shared__ float tile[32][33];
    const int bx = blockIdx.x * 32;  // n-block
    const int by = blockIdx.y * 32;  // k-block
    const int tx = threadIdx.x, ty = threadIdx.y;
#pragma unroll
    for (int j = 0; j < 4; j++)
        tile[ty + j * 8][tx] = in[(size_t)(by + ty + j * 8) * NDIM + bx + tx];
    __syncthreads();
#pragma unroll
    for (int j = 0; j < 4; j++)
        out[(size_t)(bx + ty + j * 8) * KDIM + by + tx] = rna_tf32(tile[tx][ty + j * 8]);
}

// ---------------------------------------------------------------------------
// TF32 tensor-core GEMM.
//   DUAL=true : C = rna( sigmoid(A@B0^T + bias0) * (A@B1^T + bias1) )   (g production)
//   DUAL=false: C = A@B0^T + bias0                                       (final output)
// A: [M][K] row-major (pre-rounded).  Bt: [N][K] row-major (transposed, pre-rounded).
// BM=128, BK=32, 256 threads, warp grid 4(m) x 2(n), warp tile 32 x (BN/2).
// ---------------------------------------------------------------------------
template <bool DUAL, int BN>
__global__ __launch_bounds__(256, 1)
void gemm_tf32(const float* __restrict__ A, const float* __restrict__ Bt0,
               const float* __restrict__ Bt1, const float* __restrict__ bias0,
               const float* __restrict__ bias1, float* __restrict__ C) {
    constexpr int BM = 128, BK = 32, THREADS = 256, NSTAGE = 3;
    constexpr int WN = BN / 2;
    constexpr int NT = WN / 8;                 // n8-tiles per warp (4 or 8)
    constexpr int PITCH = 144;                 // bytes per smem row (36 floats: BK + 4 pad)
    constexpr int A_BYTES = BM * PITCH;        // 18432
    constexpr int B_BYTES = BN * PITCH;
    constexpr int NB = DUAL ? 2 : 1;
    constexpr int STAGE = A_BYTES + B_BYTES * NB;
    constexpr int KT = KDIM / BK;              // 32
    constexpr int ALD = BM * 8 / THREADS;      // 4
    constexpr int BLD = BN * 8 / THREADS;      // 2 (BN=64) or 4 (BN=128)

    extern __shared__ char smem[];
    const int tid  = threadIdx.x;
    const int lane = tid & 31, warp = tid >> 5;
    const int wm = warp >> 1, wn = warp & 1;
    const int mBase = blockIdx.y * BM, nBase = blockIdx.x * BN;

    const uint32_t sBase = (uint32_t)__cvta_generic_to_shared(smem);

    // lane-dependent ldmatrix source offsets (bytes within a stage)
    const int lt = lane >> 3, lr = lane & 7;
    const uint32_t aOff = (uint32_t)((wm * 32 + (lt & 1) * 8 + lr) * PITCH + (lt >> 1) * 16);
    const uint32_t bOff = (uint32_t)(A_BYTES + (wn * WN + (lt >> 1) * 8 + lr) * PITCH + (lt & 1) * 16);

    auto load_stage = [&](int st, int k0) {
        const uint32_t sb = sBase + st * STAGE;
#pragma unroll
        for (int i = 0; i < ALD; i++) {
            const int ch = tid + i * THREADS;
            const int row = ch >> 3, kc = (ch & 7) * 4;
            cp16(sb + row * PITCH + kc * 4,
                 A + (size_t)(mBase + row) * KDIM + k0 + kc);
        }
#pragma unroll
        for (int i = 0; i < BLD; i++) {
            const int ch = tid + i * THREADS;
            const int row = ch >> 3, kc = (ch & 7) * 4;
            const size_t g = (size_t)(nBase + row) * KDIM + k0 + kc;
            const uint32_t sa = sb + A_BYTES + row * PITCH + kc * 4;
            cp16(sa, Bt0 + g);
            if constexpr (DUAL) cp16(sa + B_BYTES, Bt1 + g);
        }
    };

    float acc0[2][NT][4];
    float acc1[2][DUAL ? NT : 1][4];
#pragma unroll
    for (int mt = 0; mt < 2; mt++)
#pragma unroll
        for (int nt = 0; nt < NT; nt++)
#pragma unroll
            for (int i = 0; i < 4; i++) {
                acc0[mt][nt][i] = 0.0f;
                if constexpr (DUAL) acc1[mt][nt][i] = 0.0f;
            }

    load_stage(0, 0);
    asm volatile("cp.async.commit_group;");
    load_stage(1, BK);
    asm volatile("cp.async.commit_group;");

    int cmp_st = 0, ld_st = 2;
#pragma unroll 1
    for (int kt = 0; kt < KT; kt++) {
        asm volatile("cp.async.wait_group 1;");
        __syncthreads();

        if (kt + 2 < KT) load_stage(ld_st, (kt + 2) * BK);
        asm volatile("cp.async.commit_group;");

        const uint32_t sb = sBase + cmp_st * STAGE;
#pragma unroll
        for (int kk = 0; kk < 4; kk++) {
            uint32_t a[2][4];
            ldsm4(a[0], sb + aOff + kk * 32);
            ldsm4(a[1], sb + aOff + 16 * PITCH + kk * 32);

            uint32_t b[NT / 2][4];
#pragma unroll
            for (int np = 0; np < NT / 2; np++)
                ldsm4(b[np], sb + bOff + np * 16 * PITCH + kk * 32);
#pragma unroll
            for (int mt = 0; mt < 2; mt++)
#pragma unroll
                for (int nt = 0; nt < NT; nt++)
                    mma_tf32(acc0[mt][nt], a[mt],
                             b[nt >> 1][(nt & 1) * 2], b[nt >> 1][(nt & 1) * 2 + 1]);

            if constexpr (DUAL) {
#pragma unroll
                for (int np = 0; np < NT / 2; np++)
                    ldsm4(b[np], sb + bOff + B_BYTES + np * 16 * PITCH + kk * 32);
#pragma unroll
                for (int mt = 0; mt < 2; mt++)
#pragma unroll
                    for (int nt = 0; nt < NT; nt++)
                        mma_tf32(acc1[mt][nt], a[mt],
                                 b[nt >> 1][(nt & 1) * 2], b[nt >> 1][(nt & 1) * 2 + 1]);
            }
        }
        cmp_st = (cmp_st == NSTAGE - 1) ? 0 : cmp_st + 1;
        ld_st  = (ld_st  == NSTAGE - 1) ? 0 : ld_st  + 1;
    }

    // epilogue: c0,c1 at (row g, cols 2t,2t+1); c2,c3 at row g+8
    const int r0b = mBase + wm * 32 + (lane >> 2);
    const int cb  = nBase + wn * WN + (lane & 3) * 2;
#pragma unroll
    for (int mt = 0; mt < 2; mt++) {
#pragma unroll
        for (int nt = 0; nt < NT; nt++) {
            const int c  = cb + nt * 8;
            const int r0 = r0b + mt * 16;
            const int r1 = r0 + 8;
            if constexpr (DUAL) {
                const float bq0 = bias0[c], bq1 = bias0[c + 1];
                const float bv0 = bias1[c], bv1 = bias1[c + 1];
                const float g00 = rna_tf32((acc1[mt][nt][0] + bv0) * sigmf(acc0[mt][nt][0] + bq0));
                const float g01 = rna_tf32((acc1[mt][nt][1] + bv1) * sigmf(acc0[mt][nt][1] + bq1));
                const float g10 = rna_tf32((acc1[mt][nt][2] + bv0) * sigmf(acc0[mt][nt][2] + bq0));
                const float g11 = rna_tf32((acc1[mt][nt][3] + bv1) * sigmf(acc0[mt][nt][3] + bq1));
                *reinterpret_cast<float2*>(C + (size_t)r0 * NDIM + c) = make_float2(g00, g01);
                *reinterpret_cast<float2*>(C + (size_t)r1 * NDIM + c) = make_float2(g10, g11);
            } else {
                const float b0v = bias0[c], b1v = bias0[c + 1];
                *reinterpret_cast<float2*>(C + (size_t)r0 * NDIM + c) =
                    make_float2(acc0[mt][nt][0] + b0v, acc0[mt][nt][1] + b1v);
                *reinterpret_cast<float2*>(C + (size_t)r1 * NDIM + c) =
                    make_float2(acc0[mt][nt][2] + b0v, acc0[mt][nt][3] + b1v);
            }
        }
    }
}

// ---------------------------------------------------------------------------
// launch
// ---------------------------------------------------------------------------
extern "C" void kernel_launch(void* const* d_in, const int* in_sizes, int n_in,
                              void* d_out, int out_size) {
    (void)in_sizes; (void)n_in; (void)out_size;
    const float* emb = (const float*)d_in[0];
    const float* Wq  = (const float*)d_in[1];
    const float* bq  = (const float*)d_in[2];
    // d_in[3]=Wk, d_in[4]=bk, d_in[7]=w: algebraically dead (num/den cancels to v)
    const float* Wv  = (const float*)d_in[5];
    const float* bv  = (const float*)d_in[6];
    const float* Wo  = (const float*)d_in[8];
    const float* bo  = (const float*)d_in[9];
    float* out = (float*)d_out;

    float *embr, *wqt, *wvt, *wot, *mid;
    cudaGetSymbolAddress((void**)&embr, g_emb_r);
    cudaGetSymbolAddress((void**)&wqt,  g_wq_t);
    cudaGetSymbolAddress((void**)&wvt,  g_wv_t);
    cudaGetSymbolAddress((void**)&wot,  g_wo_t);
    cudaGetSymbolAddress((void**)&mid,  g_mid);

    constexpr int SMEM = 3 * (128 * 144 + 2 * 64 * 144);  // 110592 (same for both variants)
    cudaFuncSetAttribute(gemm_tf32<true, 64>,   cudaFuncAttributeMaxDynamicSharedMemorySize, SMEM);
    cudaFuncSetAttribute(gemm_tf32<false, 128>, cudaFuncAttributeMaxDynamicSharedMemorySize, SMEM);

    // prepass: rna-round emb; rna-round + transpose the 3 live weight matrices
    const int n4 = M_TOT * KDIM / 4;
    round4_kernel<<<n4 / 256, 256>>>((const float4*)emb, (float4*)embr, n4);
    dim3 tb(32, 8), tg(32, 32);
    transpose_round_kernel<<<tg, tb>>>(Wq, wqt);
    transpose_round_kernel<<<tg, tb>>>(Wv, wvt);
    transpose_round_kernel<<<tg, tb>>>(Wo, wot);

    // g = rna( sigmoid(emb@Wq + bq) * (emb@Wv + bv) )
    dim3 g1(NDIM / 64, M_TOT / 128);   // (16, 64)
    gemm_tf32<true, 64><<<g1, 256, SMEM>>>(embr, wqt, wvt, bq, bv, mid);

    // out = g @ Wo + bo
    dim3 g2(NDIM / 128, M_TOT / 128);  // (8, 64)
    gemm_tf32<false, 128><<<g2, 256, SMEM>>>(mid, wot, nullptr, bo, nullptr, out);
}

// round 7
// speedup vs baseline: 1.0016x; 1.0016x over previous
#include <cuda_runtime.h>
#include <cstdint>
#include <cstddef>

// Problem constants: B=64, S=128, D_MODEL=1024, D_INNER=1024
#define M_TOT 8192
#define KDIM  1024
#define NDIM  1024

// Scratch (allowed: __device__ globals, no allocation in kernel_launch)
__device__ __align__(16) float g_emb_r[(size_t)M_TOT * KDIM]; // rna-rounded embeddings
__device__ __align__(16) float g_wq_t[(size_t)KDIM * NDIM];   // Wq^T, rounded  [N][K]
__device__ __align__(16) float g_wv_t[(size_t)KDIM * NDIM];   // Wv^T, rounded
__device__ __align__(16) float g_wo_t[(size_t)KDIM * NDIM];   // Wo^T, rounded
__device__ __align__(16) float g_mid[(size_t)M_TOT * NDIM];   // g = sigmoid(q)*v, rounded

// ---------------------------------------------------------------------------
// helpers
// ---------------------------------------------------------------------------
__device__ __forceinline__ float rna_tf32(float x) {
    uint32_t y;
    asm("cvt.rna.tf32.f32 %0, %1;" : "=r"(y) : "f"(x));
    return __uint_as_float(y);
}

__device__ __forceinline__ void cp16(uint32_t saddr, const void* gptr) {
    asm volatile("cp.async.cg.shared.global [%0], [%1], 16;" :: "r"(saddr), "l"(gptr));
}

__device__ __forceinline__ void ldsm4(uint32_t r[4], uint32_t saddr) {
    asm volatile("ldmatrix.sync.aligned.m8n8.x4.shared.b16 {%0,%1,%2,%3}, [%4];"
                 : "=r"(r[0]), "=r"(r[1]), "=r"(r[2]), "=r"(r[3]) : "r"(saddr));
}

__device__ __forceinline__ void mma_tf32(float c[4], const uint32_t a[4],
                                         uint32_t b0, uint32_t b1) {
    asm volatile(
        "mma.sync.aligned.m16n8k8.row.col.f32.tf32.tf32.f32 "
        "{%0,%1,%2,%3},{%4,%5,%6,%7},{%8,%9},{%0,%1,%2,%3};"
        : "+f"(c[0]), "+f"(c[1]), "+f"(c[2]), "+f"(c[3])
        : "r"(a[0]), "r"(a[1]), "r"(a[2]), "r"(a[3]), "r"(b0), "r"(b1));
}

__device__ __forceinline__ float sigmf(float x) {
    return 1.0f / (1.0f + __expf(-x));
}

// ---------------------------------------------------------------------------
// Prepass kernels
// ---------------------------------------------------------------------------
__global__ void round4_kernel(const float4* __restrict__ in, float4* __restrict__ out, int n) {
    int i = blockIdx.x * blockDim.x + threadIdx.x;
    if (i < n) {
        float4 t = in[i];
        t.x = rna_tf32(t.x); t.y = rna_tf32(t.y);
        t.z = rna_tf32(t.z); t.w = rna_tf32(t.w);
        out[i] = t;
    }
}

// out[n][k] = rna(in[k][n]) for a 1024x1024 matrix
__global__ void transpose_round_kernel(const float* __restrict__ in, float* __restrict__ out) {
    __shared__ float tile[32][33];
    const int bx = blockIdx.x * 32;  // n-block
    const int by = blockIdx.y * 32;  // k-block
    const int tx = threadIdx.x, ty = threadIdx.y;
#pragma unroll
    for (int j = 0; j < 4; j++)
        tile[ty + j * 8][tx] = in[(size_t)(by + ty + j * 8) * NDIM + bx + tx];
    __syncthreads();
#pragma unroll
    for (int j = 0; j < 4; j++)
        out[(size_t)(bx + ty + j * 8) * KDIM + by + tx] = rna_tf32(tile[tx][ty + j * 8]);
}

// ---------------------------------------------------------------------------
// TF32 tensor-core GEMM.
//   DUAL=true : C = rna( sigmoid(A@B0^T + bias0) * (A@B1^T + bias1) )   (g production)
//   DUAL=false: C = A@B0^T + bias0                                       (final output)
// A: [M][K] row-major (pre-rounded).  Bt: [N][K] row-major (transposed, pre-rounded).
// BM=128, BK=32, 256 threads, warp grid 4(m) x 2(n), warp tile 32 x (BN/2).
// ---------------------------------------------------------------------------
template <bool DUAL, int BN>
__global__ __launch_bounds__(256, 1)
void gemm_tf32(const float* __restrict__ A, const float* __restrict__ Bt0,
               const float* __restrict__ Bt1, const float* __restrict__ bias0,
               const float* __restrict__ bias1, float* __restrict__ C) {
    constexpr int BM = 128, BK = 32, THREADS = 256, NSTAGE = 3;
    constexpr int WN = BN / 2;
    constexpr int NT = WN / 8;                 // n8-tiles per warp (4 or 8)
    constexpr int PITCH = 144;                 // bytes per smem row (36 floats: BK + 4 pad)
    constexpr int A_BYTES = BM * PITCH;        // 18432
    constexpr int B_BYTES = BN * PITCH;
    constexpr int NB = DUAL ? 2 : 1;
    constexpr int STAGE = A_BYTES + B_BYTES * NB;
    constexpr int KT = KDIM / BK;              // 32
    constexpr int ALD = BM * 8 / THREADS;      // 4
    constexpr int BLD = BN * 8 / THREADS;      // 2 (BN=64) or 4 (BN=128)

    extern __shared__ char smem[];
    const int tid  = threadIdx.x;
    const int lane = tid & 31, warp = tid >> 5;
    const int wm = warp >> 1, wn = warp & 1;
    const int mBase = blockIdx.y * BM, nBase = blockIdx.x * BN;

    const uint32_t sBase = (uint32_t)__cvta_generic_to_shared(smem);

    // lane-dependent ldmatrix source offsets (bytes within a stage)
    const int lt = lane >> 3, lr = lane & 7;
    const uint32_t aOff = (uint32_t)((wm * 32 + (lt & 1) * 8 + lr) * PITCH + (lt >> 1) * 16);
    const uint32_t bOff = (uint32_t)(A_BYTES + (wn * WN + (lt >> 1) * 8 + lr) * PITCH + (lt & 1) * 16);

    auto load_stage = [&](int st, int k0) {
        const uint32_t sb = sBase + st * STAGE;
#pragma unroll
        for (int i = 0; i < ALD; i++) {
            const int ch = tid + i * THREADS;
            const int row = ch >> 3, kc = (ch & 7) * 4;
            cp16(sb + row * PITCH + kc * 4,
                 A + (size_t)(mBase + row) * KDIM + k0 + kc);
        }
#pragma unroll
        for (int i = 0; i < BLD; i++) {
            const int ch = tid + i * THREADS;
            const int row = ch >> 3, kc = (ch & 7) * 4;
            const size_t g = (size_t)(nBase + row) * KDIM + k0 + kc;
            const uint32_t sa = sb + A_BYTES + row * PITCH + kc * 4;
            cp16(sa, Bt0 + g);
            if constexpr (DUAL) cp16(sa + B_BYTES, Bt1 + g);
        }
    };

    float acc0[2][NT][4];
    float acc1[2][DUAL ? NT : 1][4];
#pragma unroll
    for (int mt = 0; mt < 2; mt++)
#pragma unroll
        for (int nt = 0; nt < NT; nt++)
#pragma unroll
            for (int i = 0; i < 4; i++) {
                acc0[mt][nt][i] = 0.0f;
                if constexpr (DUAL) acc1[mt][nt][i] = 0.0f;
            }

    load_stage(0, 0);
    asm volatile("cp.async.commit_group;");
    load_stage(1, BK);
    asm volatile("cp.async.commit_group;");

    int cmp_st = 0, ld_st = 2;
#pragma unroll 1
    for (int kt = 0; kt < KT; kt++) {
        asm volatile("cp.async.wait_group 1;");
        __syncthreads();

        if (kt + 2 < KT) load_stage(ld_st, (kt + 2) * BK);
        asm volatile("cp.async.commit_group;");

        const uint32_t sb = sBase + cmp_st * STAGE;
#pragma unroll
        for (int kk = 0; kk < 4; kk++) {
            uint32_t a[2][4];
            ldsm4(a[0], sb + aOff + kk * 32);
            ldsm4(a[1], sb + aOff + 16 * PITCH + kk * 32);

            uint32_t b[NT / 2][4];
#pragma unroll
            for (int np = 0; np < NT / 2; np++)
                ldsm4(b[np], sb + bOff + np * 16 * PITCH + kk * 32);
#pragma unroll
            for (int mt = 0; mt < 2; mt++)
#pragma unroll
                for (int nt = 0; nt < NT; nt++)
                    mma_tf32(acc0[mt][nt], a[mt],
                             b[nt >> 1][(nt & 1) * 2], b[nt >> 1][(nt & 1) * 2 + 1]);

            if constexpr (DUAL) {
#pragma unroll
                for (int np = 0; np < NT / 2; np++)
                    ldsm4(b[np], sb + bOff + B_BYTES + np * 16 * PITCH + kk * 32);
#pragma unroll
                for (int mt = 0; mt < 2; mt++)
#pragma unroll
                    for (int nt = 0; nt < NT; nt++)
                        mma_tf32(acc1[mt][nt], a[mt],
                                 b[nt >> 1][(nt & 1) * 2], b[nt >> 1][(nt & 1) * 2 + 1]);
            }
        }
        cmp_st = (cmp_st == NSTAGE - 1) ? 0 : cmp_st + 1;
        ld_st  = (ld_st  == NSTAGE - 1) ? 0 : ld_st  + 1;
    }

    // epilogue: c0,c1 at (row g, cols 2t,2t+1); c2,c3 at row g+8
    const int r0b = mBase + wm * 32 + (lane >> 2);
    const int cb  = nBase + wn * WN + (lane & 3) * 2;
#pragma unroll
    for (int mt = 0; mt < 2; mt++) {
#pragma unroll
        for (int nt = 0; nt < NT; nt++) {
            const int c  = cb + nt * 8;
            const int r0 = r0b + mt * 16;
            const int r1 = r0 + 8;
            if constexpr (DUAL) {
                const float bq0 = bias0[c], bq1 = bias0[c + 1];
                const float bv0 = bias1[c], bv1 = bias1[c + 1];
                const float g00 = rna_tf32((acc1[mt][nt][0] + bv0) * sigmf(acc0[mt][nt][0] + bq0));
                const float g01 = rna_tf32((acc1[mt][nt][1] + bv1) * sigmf(acc0[mt][nt][1] + bq1));
                const float g10 = rna_tf32((acc1[mt][nt][2] + bv0) * sigmf(acc0[mt][nt][2] + bq0));
                const float g11 = rna_tf32((acc1[mt][nt][3] + bv1) * sigmf(acc0[mt][nt][3] + bq1));
                *reinterpret_cast<float2*>(C + (size_t)r0 * NDIM + c) = make_float2(g00, g01);
                *reinterpret_cast<float2*>(C + (size_t)r1 * NDIM + c) = make_float2(g10, g11);
            } else {
                const float b0v = bias0[c], b1v = bias0[c + 1];
                *reinterpret_cast<float2*>(C + (size_t)r0 * NDIM + c) =
                    make_float2(acc0[mt][nt][0] + b0v, acc0[mt][nt][1] + b1v);
                *reinterpret_cast<float2*>(C + (size_t)r1 * NDIM + c) =
                    make_float2(acc0[mt][nt][2] + b0v, acc0[mt][nt][3] + b1v);
            }
        }
    }
}

// ---------------------------------------------------------------------------
// launch
// ---------------------------------------------------------------------------
extern "C" void kernel_launch(void* const* d_in, const int* in_sizes, int n_in,
                              void* d_out, int out_size) {
    (void)in_sizes; (void)n_in; (void)out_size;
    const float* emb = (const float*)d_in[0];
    const float* Wq  = (const float*)d_in[1];
    const float* bq  = (const float*)d_in[2];
    // d_in[3]=Wk, d_in[4]=bk, d_in[7]=w: algebraically dead (num/den cancels to v)
    const float* Wv  = (const float*)d_in[5];
    const float* bv  = (const float*)d_in[6];
    const float* Wo  = (const float*)d_in[8];
    const float* bo  = (const float*)d_in[9];
    float* out = (float*)d_out;

    float *embr, *wqt, *wvt, *wot, *mid;
    cudaGetSymbolAddress((void**)&embr, g_emb_r);
    cudaGetSymbolAddress((void**)&wqt,  g_wq_t);
    cudaGetSymbolAddress((void**)&wvt,  g_wv_t);
    cudaGetSymbolAddress((void**)&wot,  g_wo_t);
    cudaGetSymbolAddress((void**)&mid,  g_mid);

    constexpr int SMEM = 3 * (128 * 144 + 2 * 64 * 144);  // 110592 (same for both variants)
    cudaFuncSetAttribute(gemm_tf32<true, 64>,   cudaFuncAttributeMaxDynamicSharedMemorySize, SMEM);
    cudaFuncSetAttribute(gemm_tf32<false, 128>, cudaFuncAttributeMaxDynamicSharedMemorySize, SMEM);

    // prepass: rna-round emb; rna-round + transpose the 3 live weight matrices
    const int n4 = M_TOT * KDIM / 4;
    round4_kernel<<<n4 / 256, 256>>>((const float4*)emb, (float4*)embr, n4);
    dim3 tb(32, 8), tg(32, 32);
    transpose_round_kernel<<<tg, tb>>>(Wq, wqt);
    transpose_round_kernel<<<tg, tb>>>(Wv, wvt);
    transpose_round_kernel<<<tg, tb>>>(Wo, wot);

    // g = rna( sigmoid(emb@Wq + bq) * (emb@Wv + bv) )
    dim3 g1(NDIM / 64, M_TOT / 128);   // (16, 64)
    gemm_tf32<true, 64><<<g1, 256, SMEM>>>(embr, wqt, wvt, bq, bv, mid);

    // out = g @ Wo + bo
    dim3 g2(NDIM / 128, M_TOT / 128);  // (8, 64)
    gemm_tf32<false, 128><<<g2, 256, SMEM>>>(mid, wot, nullptr, bo, nullptr, out);
}